// round 15
// baseline (speedup 1.0000x reference)
#include <cuda_runtime.h>

#define NCLS   8192
#define NBATCH 8192
#define THREADS 256
#define NWARPS (THREADS / 32)
#define QUARTER (NCLS / 4)          // 2048 elems per stream-quarter
#define NIT_W  (QUARTER / (32 * 4)) // 16 float4-iters per warp
#define EPSF 1e-8f
#define DEPTH_PARAM 0.1f
#define FULLMASK 0xffffffffu

// Global accumulator + completion counter. Zero-initialized at module load;
// the last-finishing row resets both before the kernel ends, so every
// kernel_launch call starts from identical state.
__device__ double       g_acc;
__device__ unsigned int g_done;

__global__ __launch_bounds__(THREADS)
void chce_fused_kernel(const float* __restrict__ y_pred,
                       const float* __restrict__ y_true,
                       const float* __restrict__ class_w,
                       const int*   __restrict__ tree_paths,
                       const int*   __restrict__ tree_lens,
                       float*       __restrict__ out,
                       int D)
{
    const int b    = blockIdx.x;
    const int tid  = threadIdx.x;
    const int lane = tid & 31;
    const int warp = tid >> 5;

    __shared__ float sh_s[4];   // sum-exp partials (warps 0-3)
    __shared__ float sh_v[4];   // argmax partials  (warps 4-7)
    __shared__ int   sh_i[4];

    // Warp stream-specialization: warps 0-3 stream contiguous quarters of
    // y_pred; warps 4-7 stream contiguous quarters of y_true. Each warp's
    // requests stay within one array region -> same-page DRAM bursts.
    const int q = warp & 3;                       // quarter index

    if (warp < 4) {
        const float4* yp = reinterpret_cast<const float4*>(y_pred)
                         + (size_t)b * (NCLS / 4) + q * (QUARTER / 4);
        float sumexp = 0.0f;
        #pragma unroll
        for (int it = 0; it < NIT_W; ++it) {
            float4 p = __ldcs(&yp[it * 32 + lane]);
            sumexp += __expf(p.x) + __expf(p.y) + __expf(p.z) + __expf(p.w);
        }
        #pragma unroll
        for (int off = 16; off > 0; off >>= 1)
            sumexp += __shfl_down_sync(FULLMASK, sumexp, off);
        if (lane == 0) sh_s[q] = sumexp;
    } else {
        const float4* yt = reinterpret_cast<const float4*>(y_true)
                         + (size_t)b * (NCLS / 4) + q * (QUARTER / 4);
        const int ebase = q * QUARTER;            // element offset of quarter
        float best_v = -3.402823466e38f;
        int   best_i = 0;
        #pragma unroll
        for (int it = 0; it < NIT_W; ++it) {
            float4 t = __ldcs(&yt[it * 32 + lane]);
            const int base = ebase + (it * 32 + lane) * 4;
            if (t.x > best_v) { best_v = t.x; best_i = base + 0; }
            if (t.y > best_v) { best_v = t.y; best_i = base + 1; }
            if (t.z > best_v) { best_v = t.z; best_i = base + 2; }
            if (t.w > best_v) { best_v = t.w; best_i = base + 3; }
        }
        #pragma unroll
        for (int off = 16; off > 0; off >>= 1) {
            float ov = __shfl_down_sync(FULLMASK, best_v, off);
            int   oi = __shfl_down_sync(FULLMASK, best_i, off);
            if (ov > best_v || (ov == best_v && oi < best_i)) { best_v = ov; best_i = oi; }
        }
        if (lane == 0) { sh_v[q] = best_v; sh_i[q] = best_i; }
    }
    __syncthreads();

    // ---- Parallel epilogue: warp 0 only ----
    if (warp == 0) {
        // Combine 4 sum partials and 4 argmax partials in registers.
        float s = (lane < 4) ? sh_s[lane] : 0.0f;
        float v = (lane < 4) ? sh_v[lane] : -3.402823466e38f;
        int   i = (lane < 4) ? sh_i[lane] : 0x7fffffff;
        #pragma unroll
        for (int off = 2; off > 0; off >>= 1) {
            float os = __shfl_down_sync(FULLMASK, s, off);
            float ov = __shfl_down_sync(FULLMASK, v, off);
            int   oi = __shfl_down_sync(FULLMASK, i, off);
            s += os;
            if (ov > v || (ov == v && oi < i)) { v = ov; i = oi; }
        }
        const float S     = __shfl_sync(FULLMASK, s, 0);
        const int   label = __shfl_sync(FULLMASK, i, 0);
        const float invS  = 1.0f / S;

        const int len = tree_lens[label];

        // Parallel path gather: lane k handles level k (pr=0 beyond len).
        float pr = 0.0f;
        if (lane < len && lane < D) {
            const int node = tree_paths[(size_t)label * D + lane];
            pr = expf(y_pred[(size_t)b * NCLS + node]) * invS;
        }

        // Reverse inclusive suffix scan: sarr[k] = sum_{j>=k} pr[j].
        float sarr = pr;
        #pragma unroll
        for (int off = 1; off < 32; off <<= 1) {
            float t = __shfl_down_sync(FULLMASK, sarr, off);
            if (lane + off < 32) sarr += t;
        }
        float snext = __shfl_down_sync(FULLMASK, sarr, 1);
        if (lane == 31) snext = 0.0f;

        // Per-level loss terms (valid: k < len-1).
        float term = 0.0f;
        if (lane < len - 1) {
            const float cond = sarr / (snext + EPSF);
            const float h    = (float)(len - 1 - lane);
            term = expf(-DEPTH_PARAM * h) * logf(cond + EPSF);
        }
        #pragma unroll
        for (int off = 16; off > 0; off >>= 1)
            term += __shfl_down_sync(FULLMASK, term, off);

        if (lane == 0) {
            atomicAdd(&g_acc, (double)(-class_w[label] * term));

            // Last-row-done finalize: make our add visible, then count in.
            __threadfence();
            const unsigned ticket = atomicAdd(&g_done, 1u);
            if (ticket == NBATCH - 1) {
                const unsigned long long raw =
                    atomicExch(reinterpret_cast<unsigned long long*>(&g_acc), 0ull);
                const double acc = __longlong_as_double((long long)raw);
                out[0] = (float)(acc / (double)NBATCH);
                g_done = 0;   // reset for the next launch (stream-ordered)
            }
        }
    }
}

extern "C" void kernel_launch(void* const* d_in, const int* in_sizes, int n_in,
                              void* d_out, int out_size)
{
    const float* y_pred     = (const float*)d_in[0];
    const float* y_true     = (const float*)d_in[1];
    const float* class_w    = (const float*)d_in[2];
    const int*   tree_paths = (const int*)  d_in[3];
    const int*   tree_lens  = (const int*)  d_in[4];

    const int D = in_sizes[3] / NCLS;

    chce_fused_kernel<<<NBATCH, THREADS>>>(y_pred, y_true, class_w,
                                           tree_paths, tree_lens,
                                           (float*)d_out, D);
}

// round 16
// speedup vs baseline: 1.0004x; 1.0004x over previous
#include <cuda_runtime.h>

#define NCLS   8192
#define NBATCH 8192
#define THREADS 256
#define NWARPS (THREADS / 32)
#define QUARTER (NCLS / 4)          // 2048 elems per stream-quarter
#define NIT_W  (QUARTER / (32 * 4)) // 16 float4-iters per warp
#define EPSF 1e-8f
#define DEPTH_PARAM 0.1f
#define FULLMASK 0xffffffffu

// Global accumulator + completion counter. Zero-initialized at module load;
// the last-finishing row resets both before the kernel ends, so every
// kernel_launch call starts from identical state (deterministic, graph-
// capturable, allocation-free).
__device__ double       g_acc;
__device__ unsigned int g_done;

__global__ __launch_bounds__(THREADS)
void chce_fused_kernel(const float* __restrict__ y_pred,
                       const float* __restrict__ y_true,
                       const float* __restrict__ class_w,
                       const int*   __restrict__ tree_paths,
                       const int*   __restrict__ tree_lens,
                       float*       __restrict__ out,
                       int D)
{
    const int b    = blockIdx.x;
    const int tid  = threadIdx.x;
    const int lane = tid & 31;
    const int warp = tid >> 5;

    __shared__ float sh_s[4];   // sum-exp partials (warps 0-3)
    __shared__ float sh_v[4];   // argmax partials  (warps 4-7)
    __shared__ int   sh_i[4];

    // Warp stream-specialization: warps 0-3 stream contiguous quarters of
    // y_pred (sum-exp); warps 4-7 stream contiguous quarters of y_true
    // (argmax). Each warp's requests stay within one array region ->
    // same-page DRAM bursts. 32 regs, full occupancy: measured optimum.
    const int q = warp & 3;                       // quarter index

    if (warp < 4) {
        const float4* yp = reinterpret_cast<const float4*>(y_pred)
                         + (size_t)b * (NCLS / 4) + q * (QUARTER / 4);
        float sumexp = 0.0f;
        #pragma unroll
        for (int it = 0; it < NIT_W; ++it) {
            float4 p = __ldcs(&yp[it * 32 + lane]);
            sumexp += __expf(p.x) + __expf(p.y) + __expf(p.z) + __expf(p.w);
        }
        #pragma unroll
        for (int off = 16; off > 0; off >>= 1)
            sumexp += __shfl_down_sync(FULLMASK, sumexp, off);
        if (lane == 0) sh_s[q] = sumexp;
    } else {
        const float4* yt = reinterpret_cast<const float4*>(y_true)
                         + (size_t)b * (NCLS / 4) + q * (QUARTER / 4);
        const int ebase = q * QUARTER;            // element offset of quarter
        float best_v = -3.402823466e38f;
        int   best_i = 0;
        #pragma unroll
        for (int it = 0; it < NIT_W; ++it) {
            float4 t = __ldcs(&yt[it * 32 + lane]);
            const int base = ebase + (it * 32 + lane) * 4;
            if (t.x > best_v) { best_v = t.x; best_i = base + 0; }
            if (t.y > best_v) { best_v = t.y; best_i = base + 1; }
            if (t.z > best_v) { best_v = t.z; best_i = base + 2; }
            if (t.w > best_v) { best_v = t.w; best_i = base + 3; }
        }
        #pragma unroll
        for (int off = 16; off > 0; off >>= 1) {
            float ov = __shfl_down_sync(FULLMASK, best_v, off);
            int   oi = __shfl_down_sync(FULLMASK, best_i, off);
            if (ov > best_v || (ov == best_v && oi < best_i)) { best_v = ov; best_i = oi; }
        }
        if (lane == 0) { sh_v[q] = best_v; sh_i[q] = best_i; }
    }
    __syncthreads();

    // ---- Parallel epilogue: warp 0 only (fast-math tail) ----
    if (warp == 0) {
        // Combine 4 sum partials and 4 argmax partials in registers.
        float s = (lane < 4) ? sh_s[lane] : 0.0f;
        float v = (lane < 4) ? sh_v[lane] : -3.402823466e38f;
        int   i = (lane < 4) ? sh_i[lane] : 0x7fffffff;
        #pragma unroll
        for (int off = 2; off > 0; off >>= 1) {
            float os = __shfl_down_sync(FULLMASK, s, off);
            float ov = __shfl_down_sync(FULLMASK, v, off);
            int   oi = __shfl_down_sync(FULLMASK, i, off);
            s += os;
            if (ov > v || (ov == v && oi < i)) { v = ov; i = oi; }
        }
        const float S     = __shfl_sync(FULLMASK, s, 0);
        const int   label = __shfl_sync(FULLMASK, i, 0);
        const float invS  = 1.0f / S;

        const int len = __ldg(&tree_lens[label]);

        // Parallel path gather: lane k handles level k (pr=0 beyond len,
        // matching the reference node_mask).
        float pr = 0.0f;
        if (lane < len) {
            const int node = __ldg(&tree_paths[(size_t)label * D + lane]);
            pr = __expf(__ldg(&y_pred[(size_t)b * NCLS + node])) * invS;
        }

        // Reverse inclusive suffix scan: sarr[k] = sum_{j>=k} pr[j].
        float sarr = pr;
        #pragma unroll
        for (int off = 1; off < 32; off <<= 1) {
            float t = __shfl_down_sync(FULLMASK, sarr, off);
            if (lane + off < 32) sarr += t;
        }
        float snext = __shfl_down_sync(FULLMASK, sarr, 1);
        if (lane == 31) snext = 0.0f;

        // Per-level loss terms (valid: k < len-1).
        float term = 0.0f;
        if (lane < len - 1) {
            const float cond = sarr / (snext + EPSF);
            const float h    = (float)(len - 1 - lane);
            term = __expf(-DEPTH_PARAM * h) * __logf(cond + EPSF);
        }
        #pragma unroll
        for (int off = 16; off > 0; off >>= 1)
            term += __shfl_down_sync(FULLMASK, term, off);

        if (lane == 0) {
            atomicAdd(&g_acc, (double)(-__ldg(&class_w[label]) * term));

            // Last-row-done finalize: make our add visible, then count in.
            __threadfence();
            const unsigned ticket = atomicAdd(&g_done, 1u);
            if (ticket == NBATCH - 1) {
                const unsigned long long raw =
                    atomicExch(reinterpret_cast<unsigned long long*>(&g_acc), 0ull);
                const double acc = __longlong_as_double((long long)raw);
                out[0] = (float)(acc / (double)NBATCH);
                g_done = 0;   // reset for the next launch (stream-ordered)
            }
        }
    }
}

extern "C" void kernel_launch(void* const* d_in, const int* in_sizes, int n_in,
                              void* d_out, int out_size)
{
    const float* y_pred     = (const float*)d_in[0];
    const float* y_true     = (const float*)d_in[1];
    const float* class_w    = (const float*)d_in[2];
    const int*   tree_paths = (const int*)  d_in[3];
    const int*   tree_lens  = (const int*)  d_in[4];

    const int D = in_sizes[3] / NCLS;

    chce_fused_kernel<<<NBATCH, THREADS>>>(y_pred, y_true, class_w,
                                           tree_paths, tree_lens,
                                           (float*)d_out, D);
}